// round 5
// baseline (speedup 1.0000x reference)
#include <cuda_runtime.h>
#include <cuda_fp16.h>

#define DM 64
#define MAXN 131072
#define MAXE 2097152
#define SCAN_BS 1024
#define MAXBLK 256

// ---------------- scratch (device globals) ----------------------------------
__device__ int    g_ecnt[MAXN];
__device__ int    g_fill[MAXN];
__device__ int    g_rowptr[MAXN + 1];
__device__ int    g_bsum[MAXBLK];
__device__ float  g_dis[MAXN];
__device__ int    g_csrc[MAXE];
__device__ __half g_bufA[(size_t)MAXN * DM];
__device__ __half g_bufB[(size_t)MAXN * DM];
__device__ float  g_W12[DM * DM];     // W1 @ W2
__device__ float  g_W012[DM * DM];    // W0 @ W1 @ W2
__device__ float  g_bv0[DM];          // b0 @ W1 @ W2
__device__ float  g_bv1[DM];          // b1 @ W2
__device__ float  g_s1[MAXN];         // s1 = S 1
__device__ float  g_t [MAXN];         // t  = dis * s1
__device__ float  g_s2[MAXN];         // s2 = S s1

// ---------------- preprocessing ----------------------------------------------
__global__ void k_count(const int* __restrict__ dst, int E) {
    int i = blockIdx.x * blockDim.x + threadIdx.x;
    if (i < E) atomicAdd(&g_ecnt[dst[i]], 1);
}

// per-1024-chunk sums via warp shuffles (256 threads, int4 loads)
__global__ __launch_bounds__(256) void k_scan1(int n) {
    __shared__ int ws[8];
    int t = threadIdx.x;
    int base = blockIdx.x * SCAN_BS + t * 4;
    int4 v = make_int4(0, 0, 0, 0);
    if (base + 3 < n) v = *(const int4*)(g_ecnt + base);
    else {
        if (base     < n) v.x = g_ecnt[base];
        if (base + 1 < n) v.y = g_ecnt[base + 1];
        if (base + 2 < n) v.z = g_ecnt[base + 2];
    }
    int s = v.x + v.y + v.z + v.w;
#pragma unroll
    for (int o = 16; o > 0; o >>= 1) s += __shfl_down_sync(0xffffffffu, s, o);
    if ((t & 31) == 0) ws[t >> 5] = s;
    __syncthreads();
    if (t < 8) {
        int x = ws[t];
#pragma unroll
        for (int o = 4; o > 0; o >>= 1) x += __shfl_down_sync(0xffu, x, o);
        if (t == 0) g_bsum[blockIdx.x] = x;
    }
}

__global__ void k_scan2(int nb) {
    __shared__ int sh[MAXBLK];
    int t = threadIdx.x;
    sh[t] = (t < nb) ? g_bsum[t] : 0;
    __syncthreads();
    for (int off = 1; off < MAXBLK; off <<= 1) {
        int v = (t >= off) ? sh[t - off] : 0;
        __syncthreads();
        sh[t] += v;
        __syncthreads();
    }
    g_bsum[t] = (t == 0) ? 0 : sh[t - 1];
}

// intra-block scan + rowptr; also emits dis = rsqrt(deg+1)
__global__ void k_scan3(int n) {
    __shared__ int sh[SCAN_BS];
    int t = threadIdx.x;
    int i = blockIdx.x * SCAN_BS + t;
    int v = (i < n) ? g_ecnt[i] : 0;
    sh[t] = v;
    __syncthreads();
    for (int off = 1; off < SCAN_BS; off <<= 1) {
        int u = (t >= off) ? sh[t - off] : 0;
        __syncthreads();
        sh[t] += u;
        __syncthreads();
    }
    int incl = sh[t];
    int base = g_bsum[blockIdx.x];
    if (i < n) {
        g_rowptr[i] = base + incl - v;
        if (i == n - 1) g_rowptr[n] = base + incl;
        g_dis[i] = rsqrtf((float)(v + 1));
    }
}

__global__ void k_fill(const int* __restrict__ src, const int* __restrict__ dst, int E) {
    int e = blockIdx.x * blockDim.x + threadIdx.x;
    if (e < E) {
        int d = dst[e];
        int pos = g_rowptr[d] + atomicAdd(&g_fill[d], 1);
        g_csrc[pos] = src[e];
    }
}

// ---------------- tiny weight products ---------------------------------------
// OUT = A @ B (64x64), bv = bvec @ B  (one block, 256 threads)
__global__ __launch_bounds__(256) void k_wprod(const float* __restrict__ A,
                                               const float* __restrict__ B,
                                               const float* __restrict__ bvec,
                                               float* __restrict__ OUT,
                                               float* __restrict__ bv) {
    __shared__ float bs[DM][DM + 1];
    int t = threadIdx.x;
    for (int i = t; i < DM * DM; i += 256) bs[i >> 6][i & 63] = B[i];
    __syncthreads();
#pragma unroll
    for (int k = 0; k < 16; k++) {
        int idx = t + k * 256;
        int r = idx >> 6, c = idx & 63;
        float acc = 0.f;
#pragma unroll
        for (int m = 0; m < DM; m++) acc += A[r * DM + m] * bs[m][c];
        OUT[idx] = acc;
    }
    if (t < DM) {
        float acc = 0.f;
#pragma unroll
        for (int m = 0; m < DM; m++) acc += bvec[m] * bs[m][t];
        bv[t] = acc;
    }
}

// ---------------- scalar bias chains ------------------------------------------
__global__ void k_s1k(int n) {
    int i = blockIdx.x * blockDim.x + threadIdx.x;
    if (i >= n) return;
    float di = g_dis[i];
    float u = di;
    int p = g_rowptr[i], e = g_rowptr[i + 1];
    for (; p + 3 < e; p += 4)
        u += g_dis[g_csrc[p]] + g_dis[g_csrc[p + 1]] + g_dis[g_csrc[p + 2]] + g_dis[g_csrc[p + 3]];
    for (; p < e; p++) u += g_dis[g_csrc[p]];
    float s1 = di * u;
    g_s1[i] = s1;
    g_t[i]  = di * s1;
}

__global__ void k_s2k(int n) {
    int i = blockIdx.x * blockDim.x + threadIdx.x;
    if (i >= n) return;
    float u = g_t[i];
    int p = g_rowptr[i], e = g_rowptr[i + 1];
    for (; p + 3 < e; p += 4)
        u += g_t[g_csrc[p]] + g_t[g_csrc[p + 1]] + g_t[g_csrc[p + 2]] + g_t[g_csrc[p + 3]];
    for (; p < e; p++) u += g_t[g_csrc[p]];
    g_s2[i] = g_dis[i] * u;
}

// ---------------- GEMM: A = (X @ W012) * dis[row], fp16 out --------------------
__global__ __launch_bounds__(256) void k_gemm(const float* __restrict__ X, int n) {
    __shared__ float xs[64][72];
    __shared__ float ws[64][72];
    int tid = threadIdx.x;
    int row0 = blockIdx.x * 64;

#pragma unroll
    for (int k = 0; k < 4; k++) {
        int idx = tid + k * 256;
        int r = idx >> 4;
        int c = (idx & 15) << 2;
        *(float4*)&ws[r][c] = *(const float4*)(g_W012 + r * DM + c);
        int gr = row0 + r;
        float4 xv = make_float4(0.f, 0.f, 0.f, 0.f);
        if (gr < n) xv = *(const float4*)(X + (size_t)gr * DM + c);
        *(float4*)&xs[r][c] = xv;
    }
    __syncthreads();

    int tx = tid & 15, ty = tid >> 4;
    float acc[4][4] = {};
#pragma unroll
    for (int k2 = 0; k2 < 64; k2++) {
        float a0 = xs[ty * 4 + 0][k2];
        float a1 = xs[ty * 4 + 1][k2];
        float a2 = xs[ty * 4 + 2][k2];
        float a3 = xs[ty * 4 + 3][k2];
        float4 wv = *(float4*)&ws[k2][tx * 4];
        acc[0][0] += a0 * wv.x; acc[0][1] += a0 * wv.y; acc[0][2] += a0 * wv.z; acc[0][3] += a0 * wv.w;
        acc[1][0] += a1 * wv.x; acc[1][1] += a1 * wv.y; acc[1][2] += a1 * wv.z; acc[1][3] += a1 * wv.w;
        acc[2][0] += a2 * wv.x; acc[2][1] += a2 * wv.y; acc[2][2] += a2 * wv.z; acc[2][3] += a2 * wv.w;
        acc[3][0] += a3 * wv.x; acc[3][1] += a3 * wv.y; acc[3][2] += a3 * wv.z; acc[3][3] += a3 * wv.w;
    }

#pragma unroll
    for (int i = 0; i < 4; i++) {
        int r = row0 + ty * 4 + i;
        if (r < n) {
            float s = g_dis[r];
            __half2* orow = (__half2*)(g_bufA + (size_t)r * DM);
            orow[tx * 2 + 0] = __floats2half2_rn(acc[i][0] * s, acc[i][1] * s);
            orow[tx * 2 + 1] = __floats2half2_rn(acc[i][2] * s, acc[i][3] * s);
        }
    }
}

// ---------------- S-apply passes (warp per node) --------------------------------
// input rows Gin are pre-scaled by dis[src]; output written pre-scaled (dis^2 * sum)
__global__ __launch_bounds__(256) void k_agg(const __half* __restrict__ Gin,
                                             __half* __restrict__ Gout, int n) {
    int w    = (blockIdx.x * blockDim.x + threadIdx.x) >> 5;
    int lane = threadIdx.x & 31;
    if (w >= n) return;

    int p   = g_rowptr[w];
    int end = g_rowptr[w + 1];
    const __half2* G2 = (const __half2*)Gin;
    size_t selfoff = (size_t)w * 32 + lane;

    float2 acc = __half22float2(G2[selfoff]);
    for (; p + 3 < end; p += 4) {
        int s0 = g_csrc[p], s1 = g_csrc[p + 1], s2 = g_csrc[p + 2], s3 = g_csrc[p + 3];
        float2 v0 = __half22float2(G2[(size_t)s0 * 32 + lane]);
        float2 v1 = __half22float2(G2[(size_t)s1 * 32 + lane]);
        float2 v2 = __half22float2(G2[(size_t)s2 * 32 + lane]);
        float2 v3 = __half22float2(G2[(size_t)s3 * 32 + lane]);
        acc.x += v0.x + v1.x + v2.x + v3.x;
        acc.y += v0.y + v1.y + v2.y + v3.y;
    }
    for (; p < end; p++) {
        float2 v = __half22float2(G2[(size_t)g_csrc[p] * 32 + lane]);
        acc.x += v.x; acc.y += v.y;
    }

    float dv = g_dis[w];
    float f  = dv * dv;  // dis * (apply S) then pre-scale by dis for next pass
    ((__half2*)Gout)[selfoff] = __floats2half2_rn(acc.x * f, acc.y * f);
}

// final pass: out = dis*(sum) + s2*bv0 + s1*bv1 + b2   (fp32 out)
__global__ __launch_bounds__(256) void k_aggf(const __half* __restrict__ Gin,
                                              const float* __restrict__ b2,
                                              float* __restrict__ OUT, int n) {
    int w    = (blockIdx.x * blockDim.x + threadIdx.x) >> 5;
    int lane = threadIdx.x & 31;
    if (w >= n) return;

    int p   = g_rowptr[w];
    int end = g_rowptr[w + 1];
    const __half2* G2 = (const __half2*)Gin;
    size_t selfoff = (size_t)w * 32 + lane;

    float2 acc = __half22float2(G2[selfoff]);
    for (; p + 3 < end; p += 4) {
        int s0 = g_csrc[p], s1 = g_csrc[p + 1], s2 = g_csrc[p + 2], s3 = g_csrc[p + 3];
        float2 v0 = __half22float2(G2[(size_t)s0 * 32 + lane]);
        float2 v1 = __half22float2(G2[(size_t)s1 * 32 + lane]);
        float2 v2 = __half22float2(G2[(size_t)s2 * 32 + lane]);
        float2 v3 = __half22float2(G2[(size_t)s3 * 32 + lane]);
        acc.x += v0.x + v1.x + v2.x + v3.x;
        acc.y += v0.y + v1.y + v2.y + v3.y;
    }
    for (; p < end; p++) {
        float2 v = __half22float2(G2[(size_t)g_csrc[p] * 32 + lane]);
        acc.x += v.x; acc.y += v.y;
    }

    float dv = g_dis[w];
    float c1 = g_s1[w], c2 = g_s2[w];
    float2 bv0 = ((const float2*)g_bv0)[lane];
    float2 bv1 = ((const float2*)g_bv1)[lane];
    float2 bb  = ((const float2*)b2)[lane];
    float2 o;
    o.x = dv * acc.x + c2 * bv0.x + c1 * bv1.x + bb.x;
    o.y = dv * acc.y + c2 * bv0.y + c1 * bv1.y + bb.y;
    ((float2*)OUT)[selfoff] = o;
}

// ---------------- launch --------------------------------------------------------
extern "C" void kernel_launch(void* const* d_in, const int* in_sizes, int n_in,
                              void* d_out, int out_size) {
    const float* x  = (const float*)d_in[0];
    const int*   ei = (const int*)d_in[1];
    int n = in_sizes[0] / DM;
    int E = in_sizes[1] / 2;
    const int* src = ei;
    const int* dst = ei + E;

    const float* W0 = (const float*)d_in[2];
    const float* b0 = (const float*)d_in[3];
    const float* W1 = (const float*)d_in[4];
    const float* b1 = (const float*)d_in[5];
    const float* W2 = (const float*)d_in[6];
    const float* b2 = (const float*)d_in[7];

    void *ecnt_p = nullptr, *fill_p = nullptr, *W12_p = nullptr, *W012_p = nullptr;
    void *bv0_p = nullptr, *bv1_p = nullptr, *bufA_p = nullptr, *bufB_p = nullptr;
    cudaGetSymbolAddress(&ecnt_p, g_ecnt);
    cudaGetSymbolAddress(&fill_p, g_fill);
    cudaGetSymbolAddress(&W12_p, g_W12);
    cudaGetSymbolAddress(&W012_p, g_W012);
    cudaGetSymbolAddress(&bv0_p, g_bv0);
    cudaGetSymbolAddress(&bv1_p, g_bv1);
    cudaGetSymbolAddress(&bufA_p, g_bufA);
    cudaGetSymbolAddress(&bufB_p, g_bufB);

    int nb = (n + SCAN_BS - 1) / SCAN_BS;

    cudaMemsetAsync(ecnt_p, 0, (size_t)n * sizeof(int));
    cudaMemsetAsync(fill_p, 0, (size_t)n * sizeof(int));

    k_count<<<(E + 255) / 256, 256>>>(dst, E);
    k_scan1<<<nb, 256>>>(n);
    k_scan2<<<1, MAXBLK>>>(nb);
    k_scan3<<<nb, SCAN_BS>>>(n);
    k_fill <<<(E + 255) / 256, 256>>>(src, dst, E);

    // weight products: W12 = W1@W2, bv1 = b1@W2 ; W012 = W0@W12, bv0 = b0@W12
    k_wprod<<<1, 256>>>(W1, W2, b1, (float*)W12_p, (float*)bv1_p);
    k_wprod<<<1, 256>>>(W0, (const float*)W12_p, b0, (float*)W012_p, (float*)bv0_p);

    // scalar bias chains
    k_s1k<<<(n + 255) / 256, 256>>>(n);
    k_s2k<<<(n + 255) / 256, 256>>>(n);

    int gemm_blocks = (n + 63) / 64;
    int agg_blocks  = (n + 7) / 8;

    k_gemm<<<gemm_blocks, 256>>>(x, n);                                   // x@W012 -> bufA
    k_agg <<<agg_blocks, 256>>>((const __half*)bufA_p, (__half*)bufB_p, n);
    k_agg <<<agg_blocks, 256>>>((const __half*)bufB_p, (__half*)bufA_p, n);
    k_aggf<<<agg_blocks, 256>>>((const __half*)bufA_p, b2, (float*)d_out, n);
}

// round 7
// speedup vs baseline: 1.4087x; 1.4087x over previous
#include <cuda_runtime.h>

#define DM 64
#define MAXN 131072
#define MAXE 2097152

// ---------------- scratch (device globals) ----------------------------------
// g_cnt layout: [0,MAXN) = ecnt, [MAXN,2*MAXN) = fill cursors, [2*MAXN] = scan flag
__device__ int    g_cnt[2 * MAXN + 4];
__device__ int    g_rowptr[MAXN + 1];
__device__ int    g_bsum[256];
__device__ float  g_dis[MAXN];
__device__ int    g_csrc[MAXE];
__device__ float  g_bufA[(size_t)MAXN * DM];
__device__ float  g_bufB[(size_t)MAXN * DM];
__device__ float  g_W12[DM * DM];     // W1 @ W2
__device__ float  g_W012[DM * DM];    // W0 @ W1 @ W2
__device__ float  g_bv0[DM];          // b0 @ W1 @ W2
__device__ float  g_bv1[DM];          // b1 @ W2

// ---------------- preprocessing ----------------------------------------------
__global__ void k_count(const int* __restrict__ dst, int E) {
    int i = blockIdx.x * blockDim.x + threadIdx.x;
    if (i < E) atomicAdd(&g_cnt[dst[i]], 1);
}

// single-kernel exclusive scan of g_cnt[0..n) -> g_rowptr, plus dis = rsqrt(deg+1).
// nb blocks (<=128), 256 threads, 4 items/thread. All blocks resident -> spin safe.
__global__ __launch_bounds__(256) void k_scanf(int n, int nb) {
    __shared__ int wsum[8];
    __shared__ int red[8];
    __shared__ int sbase;
    int t = threadIdx.x;
    int blk = blockIdx.x;
    int lane = t & 31, wid = t >> 5;
    int base = blk * 1024 + t * 4;

    int4 v = make_int4(0, 0, 0, 0);
    if (base + 3 < n) v = *(const int4*)(g_cnt + base);
    else {
        if (base     < n) v.x = g_cnt[base];
        if (base + 1 < n) v.y = g_cnt[base + 1];
        if (base + 2 < n) v.z = g_cnt[base + 2];
    }
    int s = v.x + v.y + v.z + v.w;

    // inclusive warp scan of s
    int sc = s;
#pragma unroll
    for (int o = 1; o < 32; o <<= 1) {
        int u = __shfl_up_sync(0xffffffffu, sc, o);
        if (lane >= o) sc += u;
    }
    if (lane == 31) wsum[wid] = sc;
    __syncthreads();
    if (t < 8) {
        int x = wsum[t];
#pragma unroll
        for (int o = 1; o < 8; o <<= 1) {
            int u = __shfl_up_sync(0xffu, x, o);
            if (t >= o) x += u;
        }
        wsum[t] = x;  // inclusive warp-sum scan
    }
    __syncthreads();
    int thr_incl = sc + (wid ? wsum[wid - 1] : 0);
    int block_total = wsum[7];

    volatile int* flag = (volatile int*)&g_cnt[2 * MAXN];
    if (t == 0) {
        g_bsum[blk] = block_total;
        __threadfence();
        atomicAdd((int*)&g_cnt[2 * MAXN], 1);
        while (*flag < nb) __nanosleep(64);
    }
    __syncthreads();

    // parallel prefix over preceding block totals
    int pv = (t < blk) ? __ldcg(&g_bsum[t]) : 0;
#pragma unroll
    for (int o = 16; o > 0; o >>= 1) pv += __shfl_down_sync(0xffffffffu, pv, o);
    if (lane == 0) red[wid] = pv;
    __syncthreads();
    if (t == 0) {
        int x = 0;
#pragma unroll
        for (int j = 0; j < 8; j++) x += red[j];
        sbase = x;
    }
    __syncthreads();

    int start = sbase + thr_incl - s;
    if (base + 3 < n) {
        int4 rp;
        rp.x = start;
        rp.y = rp.x + v.x;
        rp.z = rp.y + v.y;
        rp.w = rp.z + v.z;
        *(int4*)(g_rowptr + base) = rp;
        float4 dv;
        dv.x = rsqrtf((float)(v.x + 1));
        dv.y = rsqrtf((float)(v.y + 1));
        dv.z = rsqrtf((float)(v.z + 1));
        dv.w = rsqrtf((float)(v.w + 1));
        *(float4*)(g_dis + base) = dv;
        if (base + 4 == n) g_rowptr[n] = rp.w + v.w;
    } else {
        int e = start;
        int vv[4] = { v.x, v.y, v.z, v.w };
        for (int j = 0; j < 4; j++) {
            int i = base + j;
            if (i < n) {
                g_rowptr[i] = e;
                g_dis[i] = rsqrtf((float)(vv[j] + 1));
                e += vv[j];
                if (i == n - 1) g_rowptr[n] = e;
            }
        }
    }
}

__global__ void k_fill(const int* __restrict__ src, const int* __restrict__ dst, int E) {
    int e = blockIdx.x * blockDim.x + threadIdx.x;
    if (e < E) {
        int d = dst[e];
        int pos = g_rowptr[d] + atomicAdd(&g_cnt[MAXN + d], 1);
        g_csrc[pos] = src[e];
    }
}

// ---------------- weight products: OUT = A@B (64x64), bv = bvec@B --------------
// grid: 17 blocks. blocks 0-15: 4 rows each. block 16: bv.
__global__ __launch_bounds__(256) void k_wprod(const float* __restrict__ A,
                                               const float* __restrict__ B,
                                               const float* __restrict__ bvec,
                                               float* __restrict__ OUT,
                                               float* __restrict__ bv) {
    __shared__ float bs[DM][DM + 1];
    int t = threadIdx.x;
    for (int i = t; i < DM * DM; i += 256) bs[i >> 6][i & 63] = B[i];
    __syncthreads();
    if (blockIdx.x < 16) {
        int r = blockIdx.x * 4 + (t >> 6);
        int c = t & 63;
        float acc = 0.f;
#pragma unroll
        for (int m = 0; m < DM; m++) acc += A[r * DM + m] * bs[m][c];
        OUT[r * DM + c] = acc;
    } else if (t < DM) {
        float acc = 0.f;
#pragma unroll
        for (int m = 0; m < DM; m++) acc += bvec[m] * bs[m][t];
        bv[t] = acc;
    }
}

// ---------------- GEMM: bufA = (X @ W012) * dis[row], fp32, f32x2 FFMA ---------
#define FFMA2(acc, a, b) \
    asm("fma.rn.f32x2 %0, %1, %2, %0;" : "+l"(acc) : "l"(a), "l"(b))

__global__ __launch_bounds__(256) void k_gemm(const float* __restrict__ X, int n) {
    __shared__ float xs[64][72];
    __shared__ float ws[64][72];
    int tid = threadIdx.x;
    int row0 = blockIdx.x * 64;

#pragma unroll
    for (int k = 0; k < 4; k++) {
        int idx = tid + k * 256;
        int r = idx >> 4;
        int c = (idx & 15) << 2;
        *(float4*)&ws[r][c] = *(const float4*)(g_W012 + r * DM + c);
        int gr = row0 + r;
        float4 xv = make_float4(0.f, 0.f, 0.f, 0.f);
        if (gr < n) xv = *(const float4*)(X + (size_t)gr * DM + c);
        *(float4*)&xs[r][c] = xv;
    }
    __syncthreads();

    int tx = tid & 15, ty = tid >> 4;
    unsigned long long acc[4][2] = {};
#pragma unroll
    for (int k2 = 0; k2 < 64; k2++) {
        ulonglong2 wv = *(ulonglong2*)&ws[k2][tx * 4];
#pragma unroll
        for (int i = 0; i < 4; i++) {
            unsigned int au = __float_as_uint(xs[ty * 4 + i][k2]);
            unsigned long long ap;
            asm("mov.b64 %0, {%1, %1};" : "=l"(ap) : "r"(au));
            FFMA2(acc[i][0], ap, wv.x);
            FFMA2(acc[i][1], ap, wv.y);
        }
    }

#pragma unroll
    for (int i = 0; i < 4; i++) {
        int r = row0 + ty * 4 + i;
        if (r < n) {
            float s = g_dis[r];
            float2 p0 = *(float2*)&acc[i][0];
            float2 p1 = *(float2*)&acc[i][1];
            float4 o = make_float4(p0.x * s, p0.y * s, p1.x * s, p1.y * s);
            *(float4*)(g_bufA + (size_t)r * DM + tx * 4) = o;
        }
    }
}

// ---------------- S-apply pass (warp per node) ----------------------------------
// Gin rows pre-scaled by dis[src]. acc = self + neighbors.
// intermediate (fin=0): out = dis^2*acc + dis*c   (pre-scaled for next pass)
// final        (fin=1): out = dis*acc + c
__global__ __launch_bounds__(256) void k_agg(const float* __restrict__ Gin,
                                             const float* __restrict__ cvec,
                                             float* __restrict__ Gout,
                                             int n, int fin) {
    int w    = (blockIdx.x * blockDim.x + threadIdx.x) >> 5;
    int lane = threadIdx.x & 31;
    if (w >= n) return;

    int p   = g_rowptr[w];
    int end = g_rowptr[w + 1];
    const float2* G2 = (const float2*)Gin;
    size_t selfoff = (size_t)w * 32 + lane;

    float2 acc = G2[selfoff];
    for (; p + 3 < end; p += 4) {
        int s0 = g_csrc[p], s1 = g_csrc[p + 1], s2 = g_csrc[p + 2], s3 = g_csrc[p + 3];
        float2 v0 = G2[(size_t)s0 * 32 + lane];
        float2 v1 = G2[(size_t)s1 * 32 + lane];
        float2 v2 = G2[(size_t)s2 * 32 + lane];
        float2 v3 = G2[(size_t)s3 * 32 + lane];
        acc.x += v0.x + v1.x + v2.x + v3.x;
        acc.y += v0.y + v1.y + v2.y + v3.y;
    }
    for (; p < end; p++) {
        float2 v = G2[(size_t)g_csrc[p] * 32 + lane];
        acc.x += v.x; acc.y += v.y;
    }

    float dv = g_dis[w];
    float2 c = ((const float2*)cvec)[lane];
    float2 o;
    if (fin) {
        o.x = dv * acc.x + c.x;
        o.y = dv * acc.y + c.y;
    } else {
        float f = dv * dv;
        o.x = f * acc.x + dv * c.x;
        o.y = f * acc.y + dv * c.y;
    }
    ((float2*)Gout)[selfoff] = o;
}

// ---------------- launch --------------------------------------------------------
extern "C" void kernel_launch(void* const* d_in, const int* in_sizes, int n_in,
                              void* d_out, int out_size) {
    const float* x  = (const float*)d_in[0];
    const int*   ei = (const int*)d_in[1];
    int n = in_sizes[0] / DM;
    int E = in_sizes[1] / 2;
    const int* src = ei;
    const int* dst = ei + E;

    const float* W0 = (const float*)d_in[2];
    const float* b0 = (const float*)d_in[3];
    const float* W1 = (const float*)d_in[4];
    const float* b1 = (const float*)d_in[5];
    const float* W2 = (const float*)d_in[6];
    const float* b2 = (const float*)d_in[7];

    void *cnt_p = nullptr, *W12_p = nullptr, *W012_p = nullptr;
    void *bv0_p = nullptr, *bv1_p = nullptr, *bufA_p = nullptr, *bufB_p = nullptr;
    cudaGetSymbolAddress(&cnt_p, g_cnt);
    cudaGetSymbolAddress(&W12_p, g_W12);
    cudaGetSymbolAddress(&W012_p, g_W012);
    cudaGetSymbolAddress(&bv0_p, g_bv0);
    cudaGetSymbolAddress(&bv1_p, g_bv1);
    cudaGetSymbolAddress(&bufA_p, g_bufA);
    cudaGetSymbolAddress(&bufB_p, g_bufB);

    int nb = (n + 1023) / 1024;

    cudaMemsetAsync(cnt_p, 0, (size_t)(2 * MAXN + 4) * sizeof(int));

    k_count<<<(E + 255) / 256, 256>>>(dst, E);
    k_scanf<<<nb, 256>>>(n, nb);
    k_fill <<<(E + 255) / 256, 256>>>(src, dst, E);

    k_wprod<<<17, 256>>>(W1, W2, b1, (float*)W12_p, (float*)bv1_p);
    k_wprod<<<17, 256>>>(W0, (const float*)W12_p, b0, (float*)W012_p, (float*)bv0_p);

    int gemm_blocks = (n + 63) / 64;
    int agg_blocks  = (n + 7) / 8;

    k_gemm<<<gemm_blocks, 256>>>(x, n);  // -> bufA (pre-scaled by dis)
    k_agg <<<agg_blocks, 256>>>((const float*)bufA_p, (const float*)bv0_p, (float*)bufB_p, n, 0);
    k_agg <<<agg_blocks, 256>>>((const float*)bufB_p, (const float*)bv1_p, (float*)bufA_p, n, 0);
    k_agg <<<agg_blocks, 256>>>((const float*)bufA_p, b2, (float*)d_out, n, 1);
}